// round 2
// baseline (speedup 1.0000x reference)
#include <cuda_runtime.h>
#include <cuda_bf16.h>
#include <cstdint>

// Problem constants
#define BB 64
#define LL 512
#define TT 8
#define DD 1024
#define CC 3
#define NHOP 6
#define NPROJ 24          // [w_a, u_0..u_4, z_{c,k} c=0..2 k=0..5]

// Scratch (device globals — no allocation allowed)
__device__ float g_U[7 * DD * 4];      // levels 0..6 of [w_b, wout0, wout1, wout2], layout [(lvl*D+d)*4+c]
__device__ float g_Proj[NPROJ * DD];   // packed projection matrix [p][d]
__device__ float g_P[(size_t)BB * LL * NPROJ];  // per-row projected dots (incl. v_loc)

// ---------------------------------------------------------------------------
// K0: level-0 vectors: col0 = w_b = w_attn[D:2D], col 1+c = W_out[:,c]
// ---------------------------------------------------------------------------
__global__ void k_init(const float* __restrict__ w_attn,
                       const float* __restrict__ W_out) {
    int d = blockIdx.x * blockDim.x + threadIdx.x;
    if (d < DD) {
        g_U[d * 4 + 0] = w_attn[DD + d];
        g_U[d * 4 + 1] = W_out[d * CC + 0];
        g_U[d * 4 + 2] = W_out[d * CC + 1];
        g_U[d * 4 + 3] = W_out[d * CC + 2];
    }
}

// ---------------------------------------------------------------------------
// K1: one chain step: level k+1 = W_lin @ level k  (4 columns at once)
//     y[i][c] = sum_j W[i*D+j] * x[j][c]
// ---------------------------------------------------------------------------
__global__ void __launch_bounds__(256) k_chain(const float* __restrict__ W, int k) {
    __shared__ float4 sx[DD];
    int tid = threadIdx.x;
    const float4* xsrc = (const float4*)(g_U + (size_t)k * DD * 4);
    for (int i = tid; i < DD; i += 256) sx[i] = xsrc[i];
    __syncthreads();

    int warp = tid >> 5, lane = tid & 31;
    int row = blockIdx.x * 8 + warp;     // 128 blocks * 8 warps = 1024 rows
    float ax = 0.f, ay = 0.f, az = 0.f, aw = 0.f;
    const float* wr = W + (size_t)row * DD;
    for (int j = lane; j < DD; j += 32) {
        float w = wr[j];
        float4 x = sx[j];
        ax += w * x.x; ay += w * x.y; az += w * x.z; aw += w * x.w;
    }
    #pragma unroll
    for (int off = 16; off; off >>= 1) {
        ax += __shfl_xor_sync(0xffffffffu, ax, off);
        ay += __shfl_xor_sync(0xffffffffu, ay, off);
        az += __shfl_xor_sync(0xffffffffu, az, off);
        aw += __shfl_xor_sync(0xffffffffu, aw, off);
    }
    if (lane == 0) {
        float4* dst = (float4*)(g_U + (size_t)(k + 1) * DD * 4);
        dst[row] = make_float4(ax, ay, az, aw);
    }
}

// ---------------------------------------------------------------------------
// K2: pack projections: p=0 -> w_a; p=1..5 -> u_{p-1}; p=6+c*6+k -> z_{c,k}
// ---------------------------------------------------------------------------
__global__ void k_build_proj(const float* __restrict__ w_attn) {
    int i = blockIdx.x * blockDim.x + threadIdx.x;   // 96*256 = 24576 = 24*1024
    if (i >= NPROJ * DD) return;
    int p = i >> 10, d = i & (DD - 1);
    float v;
    if (p == 0)      v = w_attn[d];
    else if (p < 6)  v = g_U[((size_t)(p - 1) * DD + d) * 4 + 0];
    else {
        int c = (p - 6) / 6, k = (p - 6) % 6;
        v = g_U[((size_t)k * DD + d) * 4 + 1 + c];
    }
    g_Proj[i] = v;
}

// ---------------------------------------------------------------------------
// K3 (heavy): P[row][p] = v_loc(row) * dot(E[ctx[row]], Proj[p]) for 24 projs.
// CTA = 16 rows, full D in 16 chunks of 64. Thread tile: 4 rows x 6 projs x
// float4 d-slice  -> 96 FMA per 10 LDS.128 (FMA-bound, not smem-bound).
// ---------------------------------------------------------------------------
__global__ void __launch_bounds__(256) k_heavy(const int* __restrict__ ctx_ids,
                                               const float* __restrict__ E,
                                               const int* __restrict__ ctx_len,
                                               const int* __restrict__ tgt_off) {
    __shared__ float se[16][64];
    __shared__ float sp[24][64];
    __shared__ int   sid[16];

    int tid = threadIdx.x;
    int row0 = blockIdx.x * 16;
    if (tid < 16) sid[tid] = ctx_ids[row0 + tid];

    int dl = tid & 15;          // d-slice lane (16 x float4 = 64 floats)
    int pg = (tid >> 4) & 3;    // projection group (6 each)
    int rg = tid >> 6;          // row group (4 each)

    float acc[4][6];
    #pragma unroll
    for (int r = 0; r < 4; r++)
        #pragma unroll
        for (int p = 0; p < 6; p++) acc[r][p] = 0.f;

    for (int ch = 0; ch < 16; ch++) {
        __syncthreads();
        {   // load E tile: 16 rows x 64 floats = 256 float4
            int r = tid >> 4, f = tid & 15;
            const float4* src = (const float4*)(E + (size_t)sid[r] * DD + ch * 64);
            ((float4*)se[r])[f] = src[f];
            // load Proj tile: 24 x 64 floats = 384 float4
            ((float4*)sp[r])[f] = ((const float4*)(g_Proj + (size_t)r * DD + ch * 64))[f];
            if (tid < 128) {
                int p2 = 16 + (tid >> 4), f2 = tid & 15;
                ((float4*)sp[p2])[f2] = ((const float4*)(g_Proj + (size_t)p2 * DD + ch * 64))[f2];
            }
        }
        __syncthreads();

        float4 ev[4], pv[6];
        #pragma unroll
        for (int r = 0; r < 4; r++) ev[r] = ((const float4*)se[rg * 4 + r])[dl];
        #pragma unroll
        for (int p = 0; p < 6; p++) pv[p] = ((const float4*)sp[pg * 6 + p])[dl];
        #pragma unroll
        for (int r = 0; r < 4; r++)
            #pragma unroll
            for (int p = 0; p < 6; p++) {
                float a = acc[r][p];
                a = fmaf(ev[r].x, pv[p].x, a);
                a = fmaf(ev[r].y, pv[p].y, a);
                a = fmaf(ev[r].z, pv[p].z, a);
                a = fmaf(ev[r].w, pv[p].w, a);
                acc[r][p] = a;
            }
    }

    // reduce across the 16 d-lanes (stays within 16-lane halves of the warp)
    #pragma unroll
    for (int off = 8; off; off >>= 1)
        #pragma unroll
        for (int r = 0; r < 4; r++)
            #pragma unroll
            for (int p = 0; p < 6; p++)
                acc[r][p] += __shfl_xor_sync(0xffffffffu, acc[r][p], off);

    if (dl == 0) {
        int b = row0 >> 9;
        int len = ctx_len[b];
        int toff = tgt_off[b];
        #pragma unroll
        for (int r = 0; r < 4; r++) {
            int row = row0 + rg * 4 + r;
            int l = row & (LL - 1);
            float v = 0.f;
            if (l < len) v = 1.f - fabsf((float)(l - toff)) / (float)len;
            #pragma unroll
            for (int p = 0; p < 6; p++)
                g_P[(size_t)row * NPROJ + pg * 6 + p] = acc[r][p] * v;
        }
    }
}

// ---------------------------------------------------------------------------
// K4 (solve): one CTA per batch. Computes v_aspect projections, b_lin
// projections, then runs the 6-hop scalar recursion (softmax over L=512 with
// 23 weighted-sum reductions per hop), and emits the 3 logits.
// ---------------------------------------------------------------------------
__global__ void __launch_bounds__(256) k_solve(
    const int* __restrict__ tgt_ids, const int* __restrict__ ctx_len,
    const int* __restrict__ tgt_len, const float* __restrict__ E,
    const float* __restrict__ b_attn, const float* __restrict__ b_lin,
    const float* __restrict__ b_out, float* __restrict__ out)
{
    int b = blockIdx.x, tid = threadIdx.x;
    int lane = tid & 31, warp = tid >> 5;

    __shared__ float semean[DD];
    __shared__ float sw[8][33];
    __shared__ float sq[6][23];   // sq[j][r]: attn_j . Proj[1+r]
    __shared__ float sbd[24];     // b_lin . Proj[p], p=1..23
    __shared__ float sc0[9];      // vec0.u_0..u_5 (0..5), vec0.z_{c,6} (6..8)
    __shared__ float sbcast[2];

    int len  = ctx_len[b];
    int tlen = tgt_len[b];

    // v_aspect (mean of target embeddings)
    for (int d = tid; d < DD; d += 256) {
        float s = 0.f;
        for (int t = 0; t < tlen; t++)
            s += E[(size_t)tgt_ids[b * TT + t] * DD + d];
        semean[d] = s / (float)tlen;
    }
    __syncthreads();

    // 32 dot products: 6 (vec0.u_h) + 3 (vec0.z_{c,6}) + 23 (b_lin.Proj_p)
    float part[32];
    #pragma unroll
    for (int i = 0; i < 32; i++) part[i] = 0.f;
    for (int d = tid; d < DD; d += 256) {
        float em = semean[d];
        float bl = b_lin[d];
        #pragma unroll
        for (int h = 0; h < 6; h++) part[h] += em * g_U[((size_t)h * DD + d) * 4 + 0];
        #pragma unroll
        for (int c = 0; c < 3; c++) part[6 + c] += em * g_U[((size_t)6 * DD + d) * 4 + 1 + c];
        #pragma unroll
        for (int p = 1; p < 24; p++) part[8 + p] += bl * g_Proj[(size_t)p * DD + d];
    }
    #pragma unroll
    for (int off = 16; off; off >>= 1)
        #pragma unroll
        for (int i = 0; i < 32; i++)
            part[i] += __shfl_xor_sync(0xffffffffu, part[i], off);
    if (lane == 0) {
        #pragma unroll
        for (int i = 0; i < 32; i++) sw[warp][i] = part[i];
    }
    __syncthreads();
    if (tid < 32) {
        float s = 0.f;
        #pragma unroll
        for (int w = 0; w < 8; w++) s += sw[w][tid];
        if (tid < 9) sc0[tid] = s;
        else         sbd[tid - 8] = s;     // tid 9..31 -> sbd[1..23]
    }
    __syncthreads();

    // pull this thread's 2 rows of P into registers
    int l0 = tid, l1 = tid + 256;
    float P0[24], P1[24];
    {
        const float4* p0 = (const float4*)(g_P + ((size_t)b * LL + l0) * NPROJ);
        const float4* p1 = (const float4*)(g_P + ((size_t)b * LL + l1) * NPROJ);
        #pragma unroll
        for (int i = 0; i < 6; i++) { ((float4*)P0)[i] = p0[i]; ((float4*)P1)[i] = p1[i]; }
    }
    float ba = b_attn[0];
    bool v0 = l0 < len, v1 = l1 < len;

    for (int j = 0; j < NHOP; j++) {
        float t = sc0[j] + ba;
        #pragma unroll
        for (int i = 0; i < 5; i++)
            if (i < j) { int k = j - 1 - i; t += sq[i][k] + sbd[1 + k]; }

        float s0 = v0 ? tanhf(P0[0] + t) : -1e30f;
        float s1 = v1 ? tanhf(P1[0] + t) : -1e30f;

        // block max
        float m = fmaxf(s0, s1);
        #pragma unroll
        for (int off = 16; off; off >>= 1) m = fmaxf(m, __shfl_xor_sync(0xffffffffu, m, off));
        if (lane == 0) sw[warp][0] = m;
        __syncthreads();
        if (tid == 0) {
            float mm = sw[0][0];
            for (int w = 1; w < 8; w++) mm = fmaxf(mm, sw[w][0]);
            sbcast[0] = mm;
        }
        __syncthreads();
        float M = sbcast[0];

        float e0 = v0 ? expf(s0 - M) : 0.f;
        float e1 = v1 ? expf(s1 - M) : 0.f;
        float zs = e0 + e1;
        #pragma unroll
        for (int off = 16; off; off >>= 1) zs += __shfl_xor_sync(0xffffffffu, zs, off);
        if (lane == 0) sw[warp][1] = zs;
        __syncthreads();
        if (tid == 0) {
            float Z = 0.f;
            for (int w = 0; w < 8; w++) Z += sw[w][1];
            sbcast[1] = 1.f / Z;
        }
        __syncthreads();
        float rz = sbcast[1];
        float a0 = e0 * rz, a1 = e1 * rz;

        // 23 weighted sums over L
        float wp[23];
        #pragma unroll
        for (int r = 0; r < 23; r++) wp[r] = a0 * P0[1 + r] + a1 * P1[1 + r];
        #pragma unroll
        for (int off = 16; off; off >>= 1)
            #pragma unroll
            for (int r = 0; r < 23; r++)
                wp[r] += __shfl_xor_sync(0xffffffffu, wp[r], off);
        if (lane == 0) {
            #pragma unroll
            for (int r = 0; r < 23; r++) sw[warp][r] = wp[r];
        }
        __syncthreads();
        if (tid < 23) {
            float s = 0.f;
            #pragma unroll
            for (int w = 0; w < 8; w++) s += sw[w][tid];
            sq[j][tid] = s;
        }
        __syncthreads();
    }

    // logits_c = vec0.z_{c,6} + sum_j (attn_j + b_lin).z_{c,5-j} + b_out_c
    if (tid < CC) {
        int c = tid;
        float lg = sc0[6 + c] + b_out[c];
        #pragma unroll
        for (int j = 0; j < NHOP; j++) {
            int k = 5 - j;
            lg += sq[j][5 + c * 6 + k] + sbd[6 + c * 6 + k];
        }
        out[b * CC + c] = lg;
    }
}

// ---------------------------------------------------------------------------
extern "C" void kernel_launch(void* const* d_in, const int* in_sizes, int n_in,
                              void* d_out, int out_size) {
    const int*   ctx_ids = (const int*)  d_in[0];
    const int*   tgt_ids = (const int*)  d_in[1];
    const int*   ctx_len = (const int*)  d_in[2];
    const int*   tgt_len = (const int*)  d_in[3];
    const int*   tgt_off = (const int*)  d_in[4];
    const float* E       = (const float*)d_in[5];
    const float* W_lin   = (const float*)d_in[6];
    const float* b_lin   = (const float*)d_in[7];
    const float* w_attn  = (const float*)d_in[8];
    const float* b_attn  = (const float*)d_in[9];
    const float* W_out   = (const float*)d_in[10];
    const float* b_out   = (const float*)d_in[11];
    float* out = (float*)d_out;

    k_init<<<4, 256>>>(w_attn, W_out);
    for (int k = 0; k < NHOP; k++)
        k_chain<<<128, 256>>>(W_lin, k);
    k_build_proj<<<96, 256>>>(w_attn);
    k_heavy<<<(BB * LL) / 16, 256>>>(ctx_ids, E, ctx_len, tgt_off);
    k_solve<<<BB, 256>>>(tgt_ids, ctx_len, tgt_len, E, b_attn, b_lin, b_out, out);
}